// round 1
// baseline (speedup 1.0000x reference)
#include <cuda_runtime.h>

// Problem constants (from reference): dim=4096, MAX_DIM=32, N_COMP=10000.
// gather_idx / gather_sign are [32,32,32] row-major (k,i,j).
// Output layout: ricci[4096*4096] flattened row-major, then scalar at index 4096*4096.

#define DIMN 4096
#define MD 32

__global__ __launch_bounds__(256)
void ricci_kernel(const float* __restrict__ comp,
                  const int*   __restrict__ gidx,
                  const float* __restrict__ gsgn,
                  float* __restrict__ out,
                  long long out_size)
{
    const long long nvec   = out_size >> 2;                    // float4 chunks
    const long long tid    = (long long)blockIdx.x * blockDim.x + threadIdx.x;
    const long long stride = (long long)gridDim.x * blockDim.x;

    float4* __restrict__ out4 = reinterpret_cast<float4*>(out);

    for (long long v = tid; v < nvec; v += stride) {
        const long long base = v << 2;          // element index of chunk start
        const long long row  = base >> 12;      // / 4096
        const int       col  = (int)(base & 4095);

        float4 val = make_float4(0.f, 0.f, 0.f, 0.f);

        if (row < MD && col < MD) {
            // Fused gather+reduce for 4 adjacent (i, j..j+3) outputs.
            const int i = (int)row;
            float r0 = 0.f, r1 = 0.f, r2 = 0.f, r3 = 0.f;
            #pragma unroll 8
            for (int k = 0; k < MD; k++) {
                const int o = k * (MD * MD) + i * MD + col;
                r0 += gsgn[o + 0] * comp[gidx[o + 0]];
                r1 += gsgn[o + 1] * comp[gidx[o + 1]];
                r2 += gsgn[o + 2] * comp[gidx[o + 2]];
                r3 += gsgn[o + 3] * comp[gidx[o + 3]];
            }
            val = make_float4(r0, r1, r2, r3);
        }
        out4[v] = val;
    }

    // Tail elements (out_size not divisible by 4): the scalar trace lives at
    // index DIMN*DIMN; any other tail element is zero.
    for (long long e = (nvec << 2) + tid; e < out_size; e += stride) {
        float vv = 0.f;
        if (e == (long long)DIMN * DIMN) {
            float s = 0.f;
            #pragma unroll 4
            for (int i = 0; i < MD; i++) {
                #pragma unroll 8
                for (int k = 0; k < MD; k++) {
                    const int o = k * (MD * MD) + i * MD + i;
                    s += gsgn[o] * comp[gidx[o]];
                }
            }
            vv = s;
        }
        out[e] = vv;
    }
}

extern "C" void kernel_launch(void* const* d_in, const int* in_sizes, int n_in,
                              void* d_out, int out_size)
{
    const float* comp = (const float*)d_in[0];   // components [10000] f32
    const int*   gidx = (const int*)  d_in[1];   // gather_idx [32,32,32] i32
    const float* gsgn = (const float*)d_in[2];   // gather_sign [32,32,32] f32
    // d_in[3] is dim (=4096), compile-time constant here.

    float* out = (float*)d_out;
    const long long n = (long long)out_size;

    const int threads = 256;
    long long nvec = (n + 3) >> 2;
    long long blocks_ll = (nvec + threads - 1) / threads;
    int blocks = (int)(blocks_ll > 16384 ? 16384 : blocks_ll);
    if (blocks < 1) blocks = 1;

    ricci_kernel<<<blocks, threads>>>(comp, gidx, gsgn, out, n);
}

// round 2
// speedup vs baseline: 4.6345x; 4.6345x over previous
#include <cuda_runtime.h>

// dim=4096, MAX_DIM=32, N_COMP=10000.
// gather_idx/gather_sign: [32,32,32] row-major (k,i,j), int32/float32.
// Output: ricci[4096*4096] row-major + scalar trace at index 4096*4096.

#define DIMN 4096
#define MD 32

// Patch kernel: one block, 1024 threads. Thread (i,j) computes
//   r[i][j] = sum_k sgn[k,i,j] * comp[idx[k,i,j]]
// and writes it into the top-left 32x32 block of the (already-zeroed)
// output. Diagonal threads stash their value in shared; thread 0 sums
// the trace and writes the trailing scalar.
__global__ __launch_bounds__(1024)
void ricci_patch_kernel(const float* __restrict__ comp,
                        const int*   __restrict__ gidx,
                        const float* __restrict__ gsgn,
                        float* __restrict__ out)
{
    __shared__ float diag[MD];

    const int t = threadIdx.x;        // 0..1023
    const int i = t >> 5;             // row
    const int j = t & 31;             // col

    float r = 0.f;
    #pragma unroll
    for (int k = 0; k < MD; k++) {
        const int o = k * (MD * MD) + i * MD + j;
        r += gsgn[o] * comp[gidx[o]];
    }

    out[(long long)i * DIMN + j] = r;

    if (i == j) diag[i] = r;
    __syncthreads();

    if (t == 0) {
        float s = 0.f;
        #pragma unroll
        for (int k = 0; k < MD; k++) s += diag[k];
        out[(long long)DIMN * DIMN] = s;
    }
}

extern "C" void kernel_launch(void* const* d_in, const int* in_sizes, int n_in,
                              void* d_out, int out_size)
{
    const float* comp = (const float*)d_in[0];   // components [10000] f32
    const int*   gidx = (const int*)  d_in[1];   // gather_idx [32,32,32] i32
    const float* gsgn = (const float*)d_in[2];   // gather_sign [32,32,32] f32

    float* out = (float*)d_out;

    // Zero the whole output with the driver's fill path (graph-capturable
    // memset node; no allocation). Covers the 4096x4096 matrix AND the
    // trailing scalar slot.
    cudaMemsetAsync(out, 0, (size_t)out_size * sizeof(float));

    // Patch the 32x32 block + trace scalar (same stream -> ordered after
    // the memset).
    ricci_patch_kernel<<<1, 1024>>>(comp, gidx, gsgn, out);
}